// round 15
// baseline (speedup 1.0000x reference)
#include <cuda_runtime.h>
#include <cuda_fp16.h>
#include <math.h>

typedef unsigned long long ull;
typedef unsigned int u32;
typedef unsigned short u16;

constexpr int NB = 256, NT = 800, NH = 512;
constexpr int GRID = 136;
constexpr int NS = 3;
constexpr u32 CHW = 32768, CHH = 8192, STGB = CHW + CHH;
constexpr u32 GB_OFF = NS * STGB;           // 122880; gbuf: 4 planes x 4224 fp32
constexpr u32 MB_OFF = GB_OFF + 4 * 16896;  // 190464
constexpr u32 SMEM_DYN = MB_OFF + 64 + 16;

__device__ __align__(128) unsigned char g_w0f[16][8][CHW];
__device__ __align__(128) unsigned char g_w1f[16][16][CHW];
__device__ __align__(128) unsigned char g_wlf[8][CHW];
__device__ __align__(128) unsigned char g_h0f[2][8][8][CHH];
__device__ __align__(128) unsigned char g_h1f[2][8][8][CHH];
__device__ float g_c0[NH * NB], g_c1[NH * NB];
__device__ float g_bs0[2048], g_bs1[2048];
__device__ float g_lut[128 * 2048];
__device__ unsigned g_cnt[4];

__device__ __forceinline__ float sigf(float x) { return 1.0f / (1.0f + __expf(-x)); }
__device__ __forceinline__ float tanhf_fast(float x) {
    x = fminf(fmaxf(x, -15.0f), 15.0f);
    float e = __expf(2.0f * x);
    return (e - 1.0f) / (e + 1.0f);
}
__device__ __forceinline__ float warp_max(float v) {
    #pragma unroll
    for (int o = 16; o; o >>= 1) v = fmaxf(v, __shfl_xor_sync(0xffffffffu, v, o));
    return v;
}
__device__ __forceinline__ float warp_sum(float v) {
    #pragma unroll
    for (int o = 16; o; o >>= 1) v += __shfl_xor_sync(0xffffffffu, v, o);
    return v;
}
__device__ __forceinline__ void hsplit(float x, __half& h, __half& l) {
    h = __float2half_rn(x);
    l = __float2half_rn(x - __half2float(h));
}

__global__ void kinit(const float* __restrict__ Wih0, const float* __restrict__ Whh0,
                      const float* __restrict__ bih0, const float* __restrict__ bhh0,
                      const float* __restrict__ Wih1, const float* __restrict__ Whh1,
                      const float* __restrict__ bih1, const float* __restrict__ bhh1,
                      const float* __restrict__ Wlin) {
    int i0 = blockIdx.x * blockDim.x + threadIdx.x;
    int stride = gridDim.x * blockDim.x;
    if (i0 < 4) g_cnt[i0] = 0;
    for (int o = i0; o < 16 * 8 * 16384; o += stride) {
        int st = o >> 17, rr = o & 131071, ch = rr >> 14, e = rr & 16383;
        int hw = e & 1, r = (e >> 1) & 3, t = (e >> 3) & 31, w = (e >> 8) & 7;
        int half = (e >> 11) & 1, s = (e >> 12) & 3;
        int m = w * 16 + (t >> 2) + (r & 1) * 8;
        int kg = ch * 64 + s * 16 + (t & 3) * 2 + ((r >> 1) & 1) * 8 + hw;
        int grow = (m >> 5) * 512 + st * 32 + (m & 31);
        __half hi, lo; hsplit(Whh0[grow * 512 + kg], hi, lo);
        ((u16*)g_w0f[st][ch])[e] = __half_as_ushort(half ? lo : hi);
    }
    for (int o = i0; o < 16 * 16 * 16384; o += stride) {
        int st = o >> 18, rr = o & 262143, ch = rr >> 14, e = rr & 16383;
        int hw = e & 1, r = (e >> 1) & 3, t = (e >> 3) & 31, w = (e >> 8) & 7;
        int half = (e >> 11) & 1, s = (e >> 12) & 3;
        int m = w * 16 + (t >> 2) + (r & 1) * 8;
        int kg = ch * 64 + s * 16 + (t & 3) * 2 + ((r >> 1) & 1) * 8 + hw;
        int grow = (m >> 5) * 512 + st * 32 + (m & 31);
        float v = (kg < 512) ? Wih1[grow * 512 + kg] : Whh1[grow * 512 + kg - 512];
        __half hi, lo; hsplit(v, hi, lo);
        ((u16*)g_w1f[st][ch])[e] = __half_as_ushort(half ? lo : hi);
    }
    for (int o = i0; o < 8 * 16384; o += stride) {
        int ch = o >> 14, e = o & 16383;
        int hw = e & 1, r = (e >> 1) & 3, t = (e >> 3) & 31, w = (e >> 8) & 7;
        int half = (e >> 11) & 1, s = (e >> 12) & 3;
        int m = w * 16 + (t >> 2) + (r & 1) * 8;
        int kg = ch * 64 + s * 16 + (t & 3) * 2 + ((r >> 1) & 1) * 8 + hw;
        __half hi, lo; hsplit(Wlin[m * 512 + kg], hi, lo);
        ((u16*)g_wlf[ch])[e] = __half_as_ushort(half ? lo : hi);
    }
    for (int o = i0; o < 128 * 2048; o += stride)
        g_lut[o] = Wih0[(o & 2047) * 128 + (o >> 11)];
    for (int o = i0; o < 2048; o += stride) {
        g_bs0[o] = bih0[o] + bhh0[o];
        g_bs1[o] = bih1[o] + bhh1[o];
    }
    for (int o = i0; o < NH * NB; o += stride) { g_c0[o] = 0.f; g_c1[o] = 0.f; }
    ull* p0 = (ull*)&g_h0f[0][0][0][0];
    ull* p1 = (ull*)&g_h1f[0][0][0][0];
    for (int o = i0; o < (int)(sizeof(g_h0f) / 8); o += stride) { p0[o] = 0ull; p1[o] = 0ull; }
}

__device__ __forceinline__ void poll_epoch(int e) {
    if (e < 0) return;
    unsigned quota = (unsigned)GRID * (unsigned)((e >> 2) + 1);
    volatile unsigned* c = (volatile unsigned*)&g_cnt[e & 3];
    while (*c < quota) { __nanosleep(64); }
    __threadfence();
}

__device__ __forceinline__ void mbar_init(u32 a, u32 cnt) {
    asm volatile("mbarrier.init.shared.b64 [%0], %1;" :: "r"(a), "r"(cnt) : "memory");
}
__device__ __forceinline__ void mbar_arrive(u32 a) {
    asm volatile("mbarrier.arrive.release.cta.shared.b64 _, [%0];" :: "r"(a) : "memory");
}
__device__ __forceinline__ void wait_par(u32 mb, u32 par) {
    u32 done;
    asm volatile("{\n\t.reg .pred p;\n\t"
                 "mbarrier.try_wait.parity.acquire.cta.shared::cta.b64 p, [%1], %2;\n\t"
                 "selp.b32 %0, 1, 0, p;\n\t}" : "=r"(done) : "r"(mb), "r"(par) : "memory");
    if (!done) {
        asm volatile("{\n\t.reg .pred P1;\n\tWL_%=:\n\t"
                     "mbarrier.try_wait.parity.acquire.cta.shared::cta.b64 P1, [%0], %1, 0x989680;\n\t"
                     "@P1 bra.uni WD_%=;\n\tbra.uni WL_%=;\n\tWD_%=:\n\t}"
                     :: "r"(mb), "r"(par) : "memory");
    }
}

// ---- producer: ring-3 slots ----
__device__ __forceinline__ void p_issue(u32 smb, int g, const unsigned char* w,
                                        const unsigned char* h) {
    int use = g / 3, slot = g - use * 3;
    if (g >= 3) wait_par(smb + MB_OFF + 32 + slot * 8, (u32)((use - 1) & 1));
    u32 mbf = smb + MB_OFF + slot * 8;
    u32 wd = smb + slot * STGB;
    asm volatile("mbarrier.arrive.expect_tx.shared.b64 _, [%0], %1;" :: "r"(mbf), "r"(STGB) : "memory");
    asm volatile("cp.async.bulk.shared::cluster.global.mbarrier::complete_tx::bytes [%0], [%1], %2, [%3];"
                 :: "r"(wd), "l"(w), "r"(CHW), "r"(mbf) : "memory");
    asm volatile("cp.async.bulk.shared::cluster.global.mbarrier::complete_tx::bytes [%0], [%1], %2, [%3];"
                 :: "r"(wd + CHW), "l"(h), "r"(CHH), "r"(mbf) : "memory");
}

__device__ __forceinline__ void mma16816(float* c, const uint4& a, const uint2& b) {
    asm volatile("mma.sync.aligned.m16n8k16.row.col.f32.f16.f16.f32 "
                 "{%0,%1,%2,%3}, {%4,%5,%6,%7}, {%8,%9}, {%0,%1,%2,%3};"
                 : "+f"(c[0]), "+f"(c[1]), "+f"(c[2]), "+f"(c[3])
                 : "r"(a.x), "r"(a.y), "r"(a.z), "r"(a.w), "r"(b.x), "r"(b.y));
}

// warp = (m-group w4, k-slice s): m rows w4*32..+31, all 4 nt, one slice
__device__ __forceinline__ void compute_chunk(float acc[2][4][4], const char* stg,
                                              int w4, int t, int s) {
    const char* Bb = stg + CHW;
    uint2 bhi[4], blo[4];
    #pragma unroll
    for (int nt = 0; nt < 4; nt++) {
        bhi[nt] = *(const uint2*)(Bb + ((((s * 2 + 0) * 4 + nt) * 32 + t) << 3));
        blo[nt] = *(const uint2*)(Bb + ((((s * 2 + 1) * 4 + nt) * 32 + t) << 3));
    }
    #pragma unroll
    for (int mf = 0; mf < 2; mf++) {
        int w = w4 * 2 + mf;
        uint4 ahi = *(const uint4*)(stg + ((((s * 2 + 0) * 8 + w) * 32 + t) << 4));
        uint4 alo = *(const uint4*)(stg + ((((s * 2 + 1) * 8 + w) * 32 + t) << 4));
        #pragma unroll
        for (int nt = 0; nt < 4; nt++) {
            mma16816(acc[mf][nt], ahi, bhi[nt]);
            mma16816(acc[mf][nt], ahi, blo[nt]);
            mma16816(acc[mf][nt], alo, bhi[nt]);
        }
    }
}
__device__ __forceinline__ void c_chunk(float acc[2][4][4], char* sm, u32 smb, int g,
                                        int w4, int t, int s, int lane) {
    int use = g / 3, slot = g - use * 3;
    wait_par(smb + MB_OFF + slot * 8, (u32)(use & 1));
    compute_chunk(acc, sm + slot * STGB, w4, t, s);
    __syncwarp();
    if (lane == 0) mbar_arrive(smb + MB_OFF + 32 + slot * 8);
}
__device__ __forceinline__ void store_gbuf(float* g, float acc[2][4][4], int w4, int t, int kg) {
    float* gk = g + kg * 4224;
    int c0 = (t & 3) * 2;
    #pragma unroll
    for (int mf = 0; mf < 2; mf++) {
        int q = (w4 * 2 + mf) * 16 + (t >> 2);
        #pragma unroll
        for (int nt = 0; nt < 4; nt++) {
            int c = nt * 8 + c0;
            gk[q * 33 + c] = acc[mf][nt][0];       gk[q * 33 + c + 1] = acc[mf][nt][1];
            gk[(q + 8) * 33 + c] = acc[mf][nt][2]; gk[(q + 8) * 33 + c + 1] = acc[mf][nt][3];
        }
    }
}
__device__ __forceinline__ float gsum4(const float* g, int row, int bl) {
    return g[row * 33 + bl] + g[4224 + row * 33 + bl]
         + g[8448 + row * 33 + bl] + g[12672 + row * 33 + bl];
}
__device__ __forceinline__ void write_h2(unsigned char* cb, int u0, int bl, const float* hv) {
    int s = (u0 & 63) >> 4, kk0 = u0 & 15, r = kk0 >> 3;
    int tf = (bl & 7) * 4 + ((kk0 & 7) >> 1), nt = bl >> 3;
    __half h0, l0, h1, l1;
    hsplit(hv[0], h0, l0);
    hsplit(hv[1], h1, l1);
    u32 hiw = (u32)__half_as_ushort(h0) | ((u32)__half_as_ushort(h1) << 16);
    u32 low = (u32)__half_as_ushort(l0) | ((u32)__half_as_ushort(l1) << 16);
    *(u32*)(cb + ((((s * 2 + 0) * 4 + nt) * 32 + tf) * 8 + r * 4)) = hiw;
    *(u32*)(cb + ((((s * 2 + 1) * 4 + nt) * 32 + tf) * 8 + r * 4)) = low;
}
#define CBAR() asm volatile("bar.sync 1, 512;" ::: "memory")

__global__ void __launch_bounds__(544, 1) lstm_mma(
    const float* __restrict__ blin,
    const int* __restrict__ z, const int* __restrict__ nframes,
    float* __restrict__ out)
{
    extern __shared__ __align__(16) char sm[];
    u32 smb = (u32)__cvta_generic_to_shared(sm);
    float* gbuf = (float*)(sm + GB_OFF);
    const int tid = threadIdx.x, lane = tid & 31, wid = tid >> 5;
    const int w4 = wid & 3, kg = wid >> 2;     // consumer: m-group, k-slice
    const int blk = blockIdx.x;

    if (tid == 0) {
        #pragma unroll
        for (int s = 0; s < NS; s++) {
            mbar_init(smb + MB_OFF + s * 8, 1);        // full
            mbar_init(smb + MB_OFF + 32 + s * 8, 16);  // empty: 16 consumer warps
        }
    }
    __syncthreads();

    if (blk < 128) {
        const int st = blk >> 3, bt = blk & 7;
        if (wid == 16) {  // producer
            if (lane == 0) {
                int g = 0;
                for (int t = 0; t < NT; t++) {
                    const int rd = t & 1, wr = rd ^ 1;
                    poll_epoch(2 * t - 2);
                    for (int ch = 0; ch < 8; ch++, g++)
                        p_issue(smb, g, g_w0f[st][ch], g_h0f[rd][bt][ch]);
                    poll_epoch(2 * t - 1);
                    for (int ch = 0; ch < 8; ch++, g++)
                        p_issue(smb, g, g_w1f[st][8 + ch], g_h1f[rd][bt][ch]);
                    poll_epoch(2 * t);
                    for (int ch = 0; ch < 8; ch++, g++)
                        p_issue(smb, g, g_w1f[st][ch], g_h0f[wr][bt][ch]);
                }
            }
        } else {          // 16 consumer warps
            const int bl = tid & 31, uu2 = (tid >> 5) * 2;
            const int gb = bt * 32 + bl, hch = st >> 1;
            int g = 0;
            for (int t = 0; t < NT; t++) {
                const int rd = t & 1, wr = rd ^ 1;
                float acc[2][4][4] = {};
                for (int ch = 0; ch < 8; ch++, g++)
                    c_chunk(acc, sm, smb, g, w4, lane, kg, lane);
                store_gbuf(gbuf, acc, w4, lane, kg);
                CBAR();
                const float* lut = (t > 0) ? g_lut + (size_t)z[gb * NT + t - 1] * 2048 : nullptr;
                float hv[2];
                #pragma unroll
                for (int q = 0; q < 2; q++) {
                    int uu = uu2 + q, ug = st * 32 + uu;
                    float gi = gsum4(gbuf, uu, bl)      + g_bs0[ug];
                    float gf = gsum4(gbuf, 32 + uu, bl) + g_bs0[512 + ug];
                    float gg = gsum4(gbuf, 64 + uu, bl) + g_bs0[1024 + ug];
                    float go = gsum4(gbuf, 96 + uu, bl) + g_bs0[1536 + ug];
                    if (lut) { gi += lut[ug]; gf += lut[512 + ug]; gg += lut[1024 + ug]; go += lut[1536 + ug]; }
                    int ci = ug * NB + gb;
                    float c = g_c0[ci];
                    float cn = sigf(gf) * c + sigf(gi) * tanhf_fast(gg);
                    g_c0[ci] = cn;
                    hv[q] = sigf(go) * tanhf_fast(cn);
                }
                write_h2(g_h0f[wr][bt][hch], st * 32 + uu2, bl, hv);
                __threadfence();
                CBAR();
                if (tid == 0) atomicAdd(&g_cnt[(2 * t) & 3], 1u);

                #pragma unroll
                for (int mf = 0; mf < 2; mf++)
                    #pragma unroll
                    for (int nt = 0; nt < 4; nt++)
                        #pragma unroll
                        for (int q = 0; q < 4; q++) acc[mf][nt][q] = 0.f;
                for (int ch = 0; ch < 16; ch++, g++)
                    c_chunk(acc, sm, smb, g, w4, lane, kg, lane);
                store_gbuf(gbuf, acc, w4, lane, kg);
                CBAR();
                #pragma unroll
                for (int q = 0; q < 2; q++) {
                    int uu = uu2 + q, ug = st * 32 + uu;
                    float gi = gsum4(gbuf, uu, bl)      + g_bs1[ug];
                    float gf = gsum4(gbuf, 32 + uu, bl) + g_bs1[512 + ug];
                    float gg = gsum4(gbuf, 64 + uu, bl) + g_bs1[1024 + ug];
                    float go = gsum4(gbuf, 96 + uu, bl) + g_bs1[1536 + ug];
                    int ci = ug * NB + gb;
                    float c = g_c1[ci];
                    float cn = sigf(gf) * c + sigf(gi) * tanhf_fast(gg);
                    g_c1[ci] = cn;
                    hv[q] = sigf(go) * tanhf_fast(cn);
                }
                write_h2(g_h1f[wr][bt][hch], st * 32 + uu2, bl, hv);
                __threadfence();
                CBAR();
                if (tid == 0) atomicAdd(&g_cnt[(2 * t + 1) & 3], 1u);
            }
        }
    } else {
        // ---------- logits CTA ----------
        const int bt = blk - 128, b0 = bt * 32;
        if (wid == 16) {
            if (lane == 0) {
                int g = 0;
                for (int t = 1; t <= NT; t++) {
                    const int rd = t & 1;
                    poll_epoch(2 * t - 1);
                    for (int ch = 0; ch < 8; ch++, g++)
                        p_issue(smb, g, g_wlf[ch], g_h1f[rd][bt][ch]);
                }
            }
        } else {
            float nll[2];
            int nf2[2];
            #pragma unroll
            for (int j = 0; j < 2; j++) { nll[j] = 0.f; nf2[j] = nframes[b0 + wid * 2 + j]; }
            int g = 0;
            for (int t = 0; t <= NT; t++) {
                if (t >= 1) {
                    const int s = t - 1;
                    float acc[2][4][4] = {};
                    for (int ch = 0; ch < 8; ch++, g++)
                        c_chunk(acc, sm, smb, g, w4, lane, kg, lane);
                    store_gbuf(gbuf, acc, w4, lane, kg);
                    CBAR();
                    float bl4[4];
                    #pragma unroll
                    for (int q = 0; q < 4; q++) bl4[q] = blin[lane + 32 * q];
                    #pragma unroll
                    for (int j = 0; j < 2; j++) {
                        int blr = wid * 2 + j;
                        float lg[4];
                        #pragma unroll
                        for (int q = 0; q < 4; q++)
                            lg[q] = gsum4(gbuf, lane + 32 * q, blr) + bl4[q];
                        float m = fmaxf(fmaxf(lg[0], lg[1]), fmaxf(lg[2], lg[3]));
                        m = warp_max(m);
                        float se = 0.f;
                        #pragma unroll
                        for (int q = 0; q < 4; q++) se += __expf(lg[q] - m);
                        se = warp_sum(se);
                        float lse = m + logf(se);
                        int tgt = z[(b0 + blr) * NT + s];
                        float tl = 0.f;
                        #pragma unroll
                        for (int q = 0; q < 4; q++)
                            if (lane + 32 * q == tgt) tl = lg[q];
                        tl = warp_sum(tl);
                        if (s < nf2[j]) nll[j] += (lse - tl);
                    }
                    CBAR();
                }
                if (t < NT) {
                    CBAR();
                    if (tid == 0) {
                        atomicAdd(&g_cnt[(2 * t) & 3], 1u);
                        atomicAdd(&g_cnt[(2 * t + 1) & 3], 1u);
                    }
                }
            }
            if (lane == 0) {
                #pragma unroll
                for (int j = 0; j < 2; j++)
                    out[b0 + wid * 2 + j] = nll[j] * (1.0f / (float)NT);
            }
        }
    }
}

extern "C" void kernel_launch(void* const* d_in, const int* in_sizes, int n_in,
                              void* d_out, int out_size) {
    const float* Wih0 = (const float*)d_in[0];
    const float* Whh0 = (const float*)d_in[1];
    const float* bih0 = (const float*)d_in[2];
    const float* bhh0 = (const float*)d_in[3];
    const float* Wih1 = (const float*)d_in[4];
    const float* Whh1 = (const float*)d_in[5];
    const float* bih1 = (const float*)d_in[6];
    const float* bhh1 = (const float*)d_in[7];
    const float* Wlin = (const float*)d_in[8];
    const float* blin = (const float*)d_in[9];
    const int*   z    = (const int*)d_in[10];
    const int*   nf   = (const int*)d_in[11];
    float* out = (float*)d_out;

    cudaFuncSetAttribute(lstm_mma, cudaFuncAttributeMaxDynamicSharedMemorySize, SMEM_DYN);
    kinit<<<256, 256>>>(Wih0, Whh0, bih0, bhh0, Wih1, Whh1, bih1, bhh1, Wlin);
    lstm_mma<<<GRID, 544, SMEM_DYN>>>(blin, z, nf, out);
}

// round 16
// speedup vs baseline: 1.0398x; 1.0398x over previous
#include <cuda_runtime.h>
#include <cuda_fp16.h>
#include <math.h>

typedef unsigned long long ull;
typedef unsigned int u32;
typedef unsigned short u16;

constexpr int NB = 256, NT = 800, NH = 512;
constexpr int GRID = 136;
constexpr int NS = 4;
constexpr u32 CHW = 32768, CHH = 8192, STGB = CHW + CHH;
constexpr u32 GB_OFF = NS * STGB;           // 163840; gbuf: 4 planes x 4224 fp32
constexpr u32 MB_OFF = GB_OFF + 4 * 16896;  // 231424
constexpr u32 SMEM_DYN = MB_OFF + 64 + 16;  // 231504 <= 232448

__device__ __align__(128) unsigned char g_w0f[16][8][CHW];
__device__ __align__(128) unsigned char g_w1f[16][16][CHW];
__device__ __align__(128) unsigned char g_wlf[8][CHW];
__device__ __align__(128) unsigned char g_h0f[2][8][8][CHH];
__device__ __align__(128) unsigned char g_h1f[2][8][8][CHH];
__device__ float g_c0[NH * NB], g_c1[NH * NB];
__device__ float g_bs0[2048], g_bs1[2048];
__device__ float g_lut[128 * 2048];
__device__ unsigned g_cnt[4];

__device__ __forceinline__ float sigf(float x) { return 1.0f / (1.0f + __expf(-x)); }
__device__ __forceinline__ float tanhf_fast(float x) {
    x = fminf(fmaxf(x, -15.0f), 15.0f);
    float e = __expf(2.0f * x);
    return (e - 1.0f) / (e + 1.0f);
}
__device__ __forceinline__ float warp_max(float v) {
    #pragma unroll
    for (int o = 16; o; o >>= 1) v = fmaxf(v, __shfl_xor_sync(0xffffffffu, v, o));
    return v;
}
__device__ __forceinline__ float warp_sum(float v) {
    #pragma unroll
    for (int o = 16; o; o >>= 1) v += __shfl_xor_sync(0xffffffffu, v, o);
    return v;
}
__device__ __forceinline__ void hsplit(float x, __half& h, __half& l) {
    h = __float2half_rn(x);
    l = __float2half_rn(x - __half2float(h));
}

__global__ void kinit(const float* __restrict__ Wih0, const float* __restrict__ Whh0,
                      const float* __restrict__ bih0, const float* __restrict__ bhh0,
                      const float* __restrict__ Wih1, const float* __restrict__ Whh1,
                      const float* __restrict__ bih1, const float* __restrict__ bhh1,
                      const float* __restrict__ Wlin) {
    int i0 = blockIdx.x * blockDim.x + threadIdx.x;
    int stride = gridDim.x * blockDim.x;
    if (i0 < 4) g_cnt[i0] = 0;
    for (int o = i0; o < 16 * 8 * 16384; o += stride) {
        int st = o >> 17, rr = o & 131071, ch = rr >> 14, e = rr & 16383;
        int hw = e & 1, r = (e >> 1) & 3, t = (e >> 3) & 31, w = (e >> 8) & 7;
        int half = (e >> 11) & 1, s = (e >> 12) & 3;
        int m = w * 16 + (t >> 2) + (r & 1) * 8;
        int kg = ch * 64 + s * 16 + (t & 3) * 2 + ((r >> 1) & 1) * 8 + hw;
        int grow = (m >> 5) * 512 + st * 32 + (m & 31);
        __half hi, lo; hsplit(Whh0[grow * 512 + kg], hi, lo);
        ((u16*)g_w0f[st][ch])[e] = __half_as_ushort(half ? lo : hi);
    }
    for (int o = i0; o < 16 * 16 * 16384; o += stride) {
        int st = o >> 18, rr = o & 262143, ch = rr >> 14, e = rr & 16383;
        int hw = e & 1, r = (e >> 1) & 3, t = (e >> 3) & 31, w = (e >> 8) & 7;
        int half = (e >> 11) & 1, s = (e >> 12) & 3;
        int m = w * 16 + (t >> 2) + (r & 1) * 8;
        int kg = ch * 64 + s * 16 + (t & 3) * 2 + ((r >> 1) & 1) * 8 + hw;
        int grow = (m >> 5) * 512 + st * 32 + (m & 31);
        float v = (kg < 512) ? Wih1[grow * 512 + kg] : Whh1[grow * 512 + kg - 512];
        __half hi, lo; hsplit(v, hi, lo);
        ((u16*)g_w1f[st][ch])[e] = __half_as_ushort(half ? lo : hi);
    }
    for (int o = i0; o < 8 * 16384; o += stride) {
        int ch = o >> 14, e = o & 16383;
        int hw = e & 1, r = (e >> 1) & 3, t = (e >> 3) & 31, w = (e >> 8) & 7;
        int half = (e >> 11) & 1, s = (e >> 12) & 3;
        int m = w * 16 + (t >> 2) + (r & 1) * 8;
        int kg = ch * 64 + s * 16 + (t & 3) * 2 + ((r >> 1) & 1) * 8 + hw;
        __half hi, lo; hsplit(Wlin[m * 512 + kg], hi, lo);
        ((u16*)g_wlf[ch])[e] = __half_as_ushort(half ? lo : hi);
    }
    for (int o = i0; o < 128 * 2048; o += stride)
        g_lut[o] = Wih0[(o & 2047) * 128 + (o >> 11)];
    for (int o = i0; o < 2048; o += stride) {
        g_bs0[o] = bih0[o] + bhh0[o];
        g_bs1[o] = bih1[o] + bhh1[o];
    }
    for (int o = i0; o < NH * NB; o += stride) { g_c0[o] = 0.f; g_c1[o] = 0.f; }
    ull* p0 = (ull*)&g_h0f[0][0][0][0];
    ull* p1 = (ull*)&g_h1f[0][0][0][0];
    for (int o = i0; o < (int)(sizeof(g_h0f) / 8); o += stride) { p0[o] = 0ull; p1[o] = 0ull; }
}

__device__ __forceinline__ void poll_epoch(int e) {
    if (e < 0) return;
    unsigned quota = (unsigned)GRID * (unsigned)((e >> 2) + 1);
    volatile unsigned* c = (volatile unsigned*)&g_cnt[e & 3];
    while (*c < quota) { __nanosleep(64); }
    __threadfence();
}

__device__ __forceinline__ void mbar_init(u32 a, u32 cnt) {
    asm volatile("mbarrier.init.shared.b64 [%0], %1;" :: "r"(a), "r"(cnt) : "memory");
}
__device__ __forceinline__ void mbar_arrive(u32 a) {
    asm volatile("mbarrier.arrive.release.cta.shared.b64 _, [%0];" :: "r"(a) : "memory");
}
__device__ __forceinline__ void wait_par(u32 mb, u32 par) {
    u32 done;
    asm volatile("{\n\t.reg .pred p;\n\t"
                 "mbarrier.try_wait.parity.acquire.cta.shared::cta.b64 p, [%1], %2;\n\t"
                 "selp.b32 %0, 1, 0, p;\n\t}" : "=r"(done) : "r"(mb), "r"(par) : "memory");
    if (!done) {
        asm volatile("{\n\t.reg .pred P1;\n\tWL_%=:\n\t"
                     "mbarrier.try_wait.parity.acquire.cta.shared::cta.b64 P1, [%0], %1, 0x989680;\n\t"
                     "@P1 bra.uni WD_%=;\n\tbra.uni WL_%=;\n\tWD_%=:\n\t}"
                     :: "r"(mb), "r"(par) : "memory");
    }
}

// ---- producer: ring-4 slots ----
__device__ __forceinline__ void p_issue(u32 smb, int g, const unsigned char* w,
                                        const unsigned char* h) {
    int slot = g & 3;
    if (g >= 4) wait_par(smb + MB_OFF + 32 + slot * 8, (u32)(((g >> 2) - 1) & 1));
    u32 mbf = smb + MB_OFF + slot * 8;
    u32 wd = smb + slot * STGB;
    asm volatile("mbarrier.arrive.expect_tx.shared.b64 _, [%0], %1;" :: "r"(mbf), "r"(STGB) : "memory");
    asm volatile("cp.async.bulk.shared::cluster.global.mbarrier::complete_tx::bytes [%0], [%1], %2, [%3];"
                 :: "r"(wd), "l"(w), "r"(CHW), "r"(mbf) : "memory");
    asm volatile("cp.async.bulk.shared::cluster.global.mbarrier::complete_tx::bytes [%0], [%1], %2, [%3];"
                 :: "r"(wd + CHW), "l"(h), "r"(CHH), "r"(mbf) : "memory");
}

__device__ __forceinline__ void mma16816(float* c, const uint4& a, const uint2& b) {
    asm volatile("mma.sync.aligned.m16n8k16.row.col.f32.f16.f16.f32 "
                 "{%0,%1,%2,%3}, {%4,%5,%6,%7}, {%8,%9}, {%0,%1,%2,%3};"
                 : "+f"(c[0]), "+f"(c[1]), "+f"(c[2]), "+f"(c[3])
                 : "r"(a.x), "r"(a.y), "r"(a.z), "r"(a.w), "r"(b.x), "r"(b.y));
}

// warp = (m-group w4, k-slice s): m rows w4*32..+31, all 4 nt, one slice
__device__ __forceinline__ void compute_chunk(float acc[2][4][4], const char* stg,
                                              int w4, int t, int s) {
    const char* Bb = stg + CHW;
    uint2 bhi[4], blo[4];
    #pragma unroll
    for (int nt = 0; nt < 4; nt++) {
        bhi[nt] = *(const uint2*)(Bb + ((((s * 2 + 0) * 4 + nt) * 32 + t) << 3));
        blo[nt] = *(const uint2*)(Bb + ((((s * 2 + 1) * 4 + nt) * 32 + t) << 3));
    }
    #pragma unroll
    for (int mf = 0; mf < 2; mf++) {
        int w = w4 * 2 + mf;
        uint4 ahi = *(const uint4*)(stg + ((((s * 2 + 0) * 8 + w) * 32 + t) << 4));
        uint4 alo = *(const uint4*)(stg + ((((s * 2 + 1) * 8 + w) * 32 + t) << 4));
        #pragma unroll
        for (int nt = 0; nt < 4; nt++) {
            mma16816(acc[mf][nt], ahi, bhi[nt]);
            mma16816(acc[mf][nt], ahi, blo[nt]);
            mma16816(acc[mf][nt], alo, bhi[nt]);
        }
    }
}
__device__ __forceinline__ void c_chunk(float acc[2][4][4], char* sm, u32 smb, int g,
                                        int w4, int t, int s, int lane) {
    int slot = g & 3;
    wait_par(smb + MB_OFF + slot * 8, (u32)((g >> 2) & 1));
    compute_chunk(acc, sm + slot * STGB, w4, t, s);
    __syncwarp();
    if (lane == 0) mbar_arrive(smb + MB_OFF + 32 + slot * 8);
}
__device__ __forceinline__ void store_gbuf(float* g, float acc[2][4][4], int w4, int t, int kg) {
    float* gk = g + kg * 4224;
    int c0 = (t & 3) * 2;
    #pragma unroll
    for (int mf = 0; mf < 2; mf++) {
        int q = (w4 * 2 + mf) * 16 + (t >> 2);
        #pragma unroll
        for (int nt = 0; nt < 4; nt++) {
            int c = nt * 8 + c0;
            gk[q * 33 + c] = acc[mf][nt][0];       gk[q * 33 + c + 1] = acc[mf][nt][1];
            gk[(q + 8) * 33 + c] = acc[mf][nt][2]; gk[(q + 8) * 33 + c + 1] = acc[mf][nt][3];
        }
    }
}
__device__ __forceinline__ float gsum4(const float* g, int row, int bl) {
    return g[row * 33 + bl] + g[4224 + row * 33 + bl]
         + g[8448 + row * 33 + bl] + g[12672 + row * 33 + bl];
}
__device__ __forceinline__ void write_h2(unsigned char* cb, int u0, int bl, const float* hv) {
    int s = (u0 & 63) >> 4, kk0 = u0 & 15, r = kk0 >> 3;
    int tf = (bl & 7) * 4 + ((kk0 & 7) >> 1), nt = bl >> 3;
    __half h0, l0, h1, l1;
    hsplit(hv[0], h0, l0);
    hsplit(hv[1], h1, l1);
    u32 hiw = (u32)__half_as_ushort(h0) | ((u32)__half_as_ushort(h1) << 16);
    u32 low = (u32)__half_as_ushort(l0) | ((u32)__half_as_ushort(l1) << 16);
    *(u32*)(cb + ((((s * 2 + 0) * 4 + nt) * 32 + tf) * 8 + r * 4)) = hiw;
    *(u32*)(cb + ((((s * 2 + 1) * 4 + nt) * 32 + tf) * 8 + r * 4)) = low;
}
#define CBAR() asm volatile("bar.sync 1, 512;" ::: "memory")

__global__ void __launch_bounds__(544, 1) lstm_mma(
    const float* __restrict__ blin,
    const int* __restrict__ z, const int* __restrict__ nframes,
    float* __restrict__ out)
{
    extern __shared__ __align__(16) char sm[];
    u32 smb = (u32)__cvta_generic_to_shared(sm);
    float* gbuf = (float*)(sm + GB_OFF);
    const int tid = threadIdx.x, lane = tid & 31, wid = tid >> 5;
    const int w4 = wid & 3, kg = wid >> 2;     // consumer: m-group, k-slice
    const int blk = blockIdx.x;

    if (tid == 0) {
        #pragma unroll
        for (int s = 0; s < NS; s++) {
            mbar_init(smb + MB_OFF + s * 8, 1);        // full
            mbar_init(smb + MB_OFF + 32 + s * 8, 16);  // empty: 16 consumer warps
        }
    }
    __syncthreads();

    if (blk < 128) {
        const int st = blk >> 3, bt = blk & 7;
        if (wid == 16) {  // producer
            if (lane == 0) {
                int g = 0;
                for (int t = 0; t < NT; t++) {
                    const int rd = t & 1, wr = rd ^ 1;
                    poll_epoch(2 * t - 2);
                    for (int ch = 0; ch < 8; ch++, g++)
                        p_issue(smb, g, g_w0f[st][ch], g_h0f[rd][bt][ch]);
                    poll_epoch(2 * t - 1);
                    for (int ch = 0; ch < 8; ch++, g++)
                        p_issue(smb, g, g_w1f[st][8 + ch], g_h1f[rd][bt][ch]);
                    poll_epoch(2 * t);
                    for (int ch = 0; ch < 8; ch++, g++)
                        p_issue(smb, g, g_w1f[st][ch], g_h0f[wr][bt][ch]);
                }
            }
        } else {          // 16 consumer warps
            const int bl = tid & 31, uu2 = (tid >> 5) * 2;
            const int gb = bt * 32 + bl, hch = st >> 1;
            int g = 0;
            for (int t = 0; t < NT; t++) {
                const int rd = t & 1, wr = rd ^ 1;
                float acc[2][4][4] = {};
                for (int ch = 0; ch < 8; ch++, g++)
                    c_chunk(acc, sm, smb, g, w4, lane, kg, lane);
                store_gbuf(gbuf, acc, w4, lane, kg);
                CBAR();
                const float* lut = (t > 0) ? g_lut + (size_t)z[gb * NT + t - 1] * 2048 : nullptr;
                float hv[2];
                #pragma unroll
                for (int q = 0; q < 2; q++) {
                    int uu = uu2 + q, ug = st * 32 + uu;
                    float gi = gsum4(gbuf, uu, bl)      + g_bs0[ug];
                    float gf = gsum4(gbuf, 32 + uu, bl) + g_bs0[512 + ug];
                    float gg = gsum4(gbuf, 64 + uu, bl) + g_bs0[1024 + ug];
                    float go = gsum4(gbuf, 96 + uu, bl) + g_bs0[1536 + ug];
                    if (lut) { gi += lut[ug]; gf += lut[512 + ug]; gg += lut[1024 + ug]; go += lut[1536 + ug]; }
                    int ci = ug * NB + gb;
                    float c = g_c0[ci];
                    float cn = sigf(gf) * c + sigf(gi) * tanhf_fast(gg);
                    g_c0[ci] = cn;
                    hv[q] = sigf(go) * tanhf_fast(cn);
                }
                write_h2(g_h0f[wr][bt][hch], st * 32 + uu2, bl, hv);
                __threadfence();
                CBAR();
                if (tid == 0) atomicAdd(&g_cnt[(2 * t) & 3], 1u);

                #pragma unroll
                for (int mf = 0; mf < 2; mf++)
                    #pragma unroll
                    for (int nt = 0; nt < 4; nt++)
                        #pragma unroll
                        for (int q = 0; q < 4; q++) acc[mf][nt][q] = 0.f;
                for (int ch = 0; ch < 16; ch++, g++)
                    c_chunk(acc, sm, smb, g, w4, lane, kg, lane);
                store_gbuf(gbuf, acc, w4, lane, kg);
                CBAR();
                #pragma unroll
                for (int q = 0; q < 2; q++) {
                    int uu = uu2 + q, ug = st * 32 + uu;
                    float gi = gsum4(gbuf, uu, bl)      + g_bs1[ug];
                    float gf = gsum4(gbuf, 32 + uu, bl) + g_bs1[512 + ug];
                    float gg = gsum4(gbuf, 64 + uu, bl) + g_bs1[1024 + ug];
                    float go = gsum4(gbuf, 96 + uu, bl) + g_bs1[1536 + ug];
                    int ci = ug * NB + gb;
                    float c = g_c1[ci];
                    float cn = sigf(gf) * c + sigf(gi) * tanhf_fast(gg);
                    g_c1[ci] = cn;
                    hv[q] = sigf(go) * tanhf_fast(cn);
                }
                write_h2(g_h1f[wr][bt][hch], st * 32 + uu2, bl, hv);
                __threadfence();
                CBAR();
                if (tid == 0) atomicAdd(&g_cnt[(2 * t + 1) & 3], 1u);
            }
        }
    } else {
        // ---------- logits CTA ----------
        const int bt = blk - 128, b0 = bt * 32;
        if (wid == 16) {
            if (lane == 0) {
                int g = 0;
                for (int t = 1; t <= NT; t++) {
                    const int rd = t & 1;
                    poll_epoch(2 * t - 1);
                    for (int ch = 0; ch < 8; ch++, g++)
                        p_issue(smb, g, g_wlf[ch], g_h1f[rd][bt][ch]);
                }
            }
        } else {
            float nll[2];
            int nf2[2];
            #pragma unroll
            for (int j = 0; j < 2; j++) { nll[j] = 0.f; nf2[j] = nframes[b0 + wid * 2 + j]; }
            int g = 0;
            for (int t = 0; t <= NT; t++) {
                if (t >= 1) {
                    const int s = t - 1;
                    float acc[2][4][4] = {};
                    for (int ch = 0; ch < 8; ch++, g++)
                        c_chunk(acc, sm, smb, g, w4, lane, kg, lane);
                    store_gbuf(gbuf, acc, w4, lane, kg);
                    CBAR();
                    float bl4[4];
                    #pragma unroll
                    for (int q = 0; q < 4; q++) bl4[q] = blin[lane + 32 * q];
                    #pragma unroll
                    for (int j = 0; j < 2; j++) {
                        int blr = wid * 2 + j;
                        float lg[4];
                        #pragma unroll
                        for (int q = 0; q < 4; q++)
                            lg[q] = gsum4(gbuf, lane + 32 * q, blr) + bl4[q];
                        float m = fmaxf(fmaxf(lg[0], lg[1]), fmaxf(lg[2], lg[3]));
                        m = warp_max(m);
                        float se = 0.f;
                        #pragma unroll
                        for (int q = 0; q < 4; q++) se += __expf(lg[q] - m);
                        se = warp_sum(se);
                        float lse = m + logf(se);
                        int tgt = z[(b0 + blr) * NT + s];
                        float tl = 0.f;
                        #pragma unroll
                        for (int q = 0; q < 4; q++)
                            if (lane + 32 * q == tgt) tl = lg[q];
                        tl = warp_sum(tl);
                        if (s < nf2[j]) nll[j] += (lse - tl);
                    }
                    CBAR();
                }
                if (t < NT) {
                    CBAR();
                    if (tid == 0) {
                        atomicAdd(&g_cnt[(2 * t) & 3], 1u);
                        atomicAdd(&g_cnt[(2 * t + 1) & 3], 1u);
                    }
                }
            }
            if (lane == 0) {
                #pragma unroll
                for (int j = 0; j < 2; j++)
                    out[b0 + wid * 2 + j] = nll[j] * (1.0f / (float)NT);
            }
        }
    }
}

extern "C" void kernel_launch(void* const* d_in, const int* in_sizes, int n_in,
                              void* d_out, int out_size) {
    const float* Wih0 = (const float*)d_in[0];
    const float* Whh0 = (const float*)d_in[1];
    const float* bih0 = (const float*)d_in[2];
    const float* bhh0 = (const float*)d_in[3];
    const float* Wih1 = (const float*)d_in[4];
    const float* Whh1 = (const float*)d_in[5];
    const float* bih1 = (const float*)d_in[6];
    const float* bhh1 = (const float*)d_in[7];
    const float* Wlin = (const float*)d_in[8];
    const float* blin = (const float*)d_in[9];
    const int*   z    = (const int*)d_in[10];
    const int*   nf   = (const int*)d_in[11];
    float* out = (float*)d_out;

    cudaFuncSetAttribute(lstm_mma, cudaFuncAttributeMaxDynamicSharedMemorySize, SMEM_DYN);
    kinit<<<256, 256>>>(Wih0, Whh0, bih0, bhh0, Wih1, Whh1, bih1, bhh1, Wlin);
    lstm_mma<<<GRID, 544, SMEM_DYN>>>(blin, z, nf, out);
}

// round 17
// speedup vs baseline: 1.3629x; 1.3108x over previous
#include <cuda_runtime.h>
#include <cuda_fp16.h>
#include <math.h>

typedef unsigned long long ull;
typedef unsigned int u32;
typedef unsigned short u16;

constexpr int NB = 256, NT = 800, NH = 512;
constexpr int GRID = 136;
constexpr int NS = 4;
constexpr u32 CHW = 32768, CHH = 4096, STGB = CHW + CHH;   // 36 KB/stage
constexpr u32 GB_OFF = NS * STGB;            // 147456; gbuf: 2 planes x 4224 fp32
constexpr u32 MB_OFF = GB_OFF + 2 * 16896;   // 181248
constexpr u32 SMEM_DYN = MB_OFF + 64 + 16;

__device__ __align__(128) unsigned char g_w0f[16][8][CHW];
__device__ __align__(128) unsigned char g_w1f[16][16][CHW];
__device__ __align__(128) unsigned char g_wlf[8][CHW];
__device__ __align__(128) unsigned char g_h0f[2][8][8][CHH];   // h (fp16 hi only)
__device__ __align__(128) unsigned char g_h1f[2][8][8][CHH];
__device__ float g_c0[NH * NB], g_c1[NH * NB];
__device__ float g_bs0[2048], g_bs1[2048];
__device__ float g_lut[128 * 2048];
__device__ unsigned g_cnt[4];

__device__ __forceinline__ float sigf(float x) { return 1.0f / (1.0f + __expf(-x)); }
__device__ __forceinline__ float tanhf_fast(float x) {
    x = fminf(fmaxf(x, -15.0f), 15.0f);
    float e = __expf(2.0f * x);
    return (e - 1.0f) / (e + 1.0f);
}
__device__ __forceinline__ float warp_max(float v) {
    #pragma unroll
    for (int o = 16; o; o >>= 1) v = fmaxf(v, __shfl_xor_sync(0xffffffffu, v, o));
    return v;
}
__device__ __forceinline__ float warp_sum(float v) {
    #pragma unroll
    for (int o = 16; o; o >>= 1) v += __shfl_xor_sync(0xffffffffu, v, o);
    return v;
}
__device__ __forceinline__ void hsplit(float x, __half& h, __half& l) {
    h = __float2half_rn(x);
    l = __float2half_rn(x - __half2float(h));
}

__global__ void kinit(const float* __restrict__ Wih0, const float* __restrict__ Whh0,
                      const float* __restrict__ bih0, const float* __restrict__ bhh0,
                      const float* __restrict__ Wih1, const float* __restrict__ Whh1,
                      const float* __restrict__ bih1, const float* __restrict__ bhh1,
                      const float* __restrict__ Wlin) {
    int i0 = blockIdx.x * blockDim.x + threadIdx.x;
    int stride = gridDim.x * blockDim.x;
    if (i0 < 4) g_cnt[i0] = 0;
    for (int o = i0; o < 16 * 8 * 16384; o += stride) {
        int st = o >> 17, rr = o & 131071, ch = rr >> 14, e = rr & 16383;
        int hw = e & 1, r = (e >> 1) & 3, t = (e >> 3) & 31, w = (e >> 8) & 7;
        int half = (e >> 11) & 1, s = (e >> 12) & 3;
        int m = w * 16 + (t >> 2) + (r & 1) * 8;
        int kg = ch * 64 + s * 16 + (t & 3) * 2 + ((r >> 1) & 1) * 8 + hw;
        int grow = (m >> 5) * 512 + st * 32 + (m & 31);
        __half hi, lo; hsplit(Whh0[grow * 512 + kg], hi, lo);
        ((u16*)g_w0f[st][ch])[e] = __half_as_ushort(half ? lo : hi);
    }
    for (int o = i0; o < 16 * 16 * 16384; o += stride) {
        int st = o >> 18, rr = o & 262143, ch = rr >> 14, e = rr & 16383;
        int hw = e & 1, r = (e >> 1) & 3, t = (e >> 3) & 31, w = (e >> 8) & 7;
        int half = (e >> 11) & 1, s = (e >> 12) & 3;
        int m = w * 16 + (t >> 2) + (r & 1) * 8;
        int kg = ch * 64 + s * 16 + (t & 3) * 2 + ((r >> 1) & 1) * 8 + hw;
        int grow = (m >> 5) * 512 + st * 32 + (m & 31);
        float v = (kg < 512) ? Wih1[grow * 512 + kg] : Whh1[grow * 512 + kg - 512];
        __half hi, lo; hsplit(v, hi, lo);
        ((u16*)g_w1f[st][ch])[e] = __half_as_ushort(half ? lo : hi);
    }
    for (int o = i0; o < 8 * 16384; o += stride) {
        int ch = o >> 14, e = o & 16383;
        int hw = e & 1, r = (e >> 1) & 3, t = (e >> 3) & 31, w = (e >> 8) & 7;
        int half = (e >> 11) & 1, s = (e >> 12) & 3;
        int m = w * 16 + (t >> 2) + (r & 1) * 8;
        int kg = ch * 64 + s * 16 + (t & 3) * 2 + ((r >> 1) & 1) * 8 + hw;
        __half hi, lo; hsplit(Wlin[m * 512 + kg], hi, lo);
        ((u16*)g_wlf[ch])[e] = __half_as_ushort(half ? lo : hi);
    }
    for (int o = i0; o < 128 * 2048; o += stride)
        g_lut[o] = Wih0[(o & 2047) * 128 + (o >> 11)];
    for (int o = i0; o < 2048; o += stride) {
        g_bs0[o] = bih0[o] + bhh0[o];
        g_bs1[o] = bih1[o] + bhh1[o];
    }
    for (int o = i0; o < NH * NB; o += stride) { g_c0[o] = 0.f; g_c1[o] = 0.f; }
    ull* p0 = (ull*)&g_h0f[0][0][0][0];
    ull* p1 = (ull*)&g_h1f[0][0][0][0];
    for (int o = i0; o < (int)(sizeof(g_h0f) / 8); o += stride) { p0[o] = 0ull; p1[o] = 0ull; }
}

__device__ __forceinline__ void poll_epoch(int e) {
    if (e < 0) return;
    unsigned quota = (unsigned)GRID * (unsigned)((e >> 2) + 1);
    volatile unsigned* c = (volatile unsigned*)&g_cnt[e & 3];
    while (*c < quota) { __nanosleep(64); }
    __threadfence();
}

__device__ __forceinline__ void mbar_init(u32 a, u32 cnt) {
    asm volatile("mbarrier.init.shared.b64 [%0], %1;" :: "r"(a), "r"(cnt) : "memory");
}
__device__ __forceinline__ void mbar_arrive(u32 a) {
    asm volatile("mbarrier.arrive.release.cta.shared.b64 _, [%0];" :: "r"(a) : "memory");
}
__device__ __forceinline__ void wait_par(u32 mb, u32 par) {
    u32 done;
    asm volatile("{\n\t.reg .pred p;\n\t"
                 "mbarrier.try_wait.parity.acquire.cta.shared::cta.b64 p, [%1], %2;\n\t"
                 "selp.b32 %0, 1, 0, p;\n\t}" : "=r"(done) : "r"(mb), "r"(par) : "memory");
    if (!done) {
        asm volatile("{\n\t.reg .pred P1;\n\tWL_%=:\n\t"
                     "mbarrier.try_wait.parity.acquire.cta.shared::cta.b64 P1, [%0], %1, 0x989680;\n\t"
                     "@P1 bra.uni WD_%=;\n\tbra.uni WL_%=;\n\tWD_%=:\n\t}"
                     :: "r"(mb), "r"(par) : "memory");
    }
}

// ---- producer: ring-4 slots ----
__device__ __forceinline__ void p_issue(u32 smb, int g, const unsigned char* w,
                                        const unsigned char* h) {
    int slot = g & 3;
    if (g >= 4) wait_par(smb + MB_OFF + 32 + slot * 8, (u32)(((g >> 2) - 1) & 1));
    u32 mbf = smb + MB_OFF + slot * 8;
    u32 wd = smb + slot * STGB;
    asm volatile("mbarrier.arrive.expect_tx.shared.b64 _, [%0], %1;" :: "r"(mbf), "r"(STGB) : "memory");
    asm volatile("cp.async.bulk.shared::cluster.global.mbarrier::complete_tx::bytes [%0], [%1], %2, [%3];"
                 :: "r"(wd), "l"(w), "r"(CHW), "r"(mbf) : "memory");
    asm volatile("cp.async.bulk.shared::cluster.global.mbarrier::complete_tx::bytes [%0], [%1], %2, [%3];"
                 :: "r"(wd + CHW), "l"(h), "r"(CHH), "r"(mbf) : "memory");
}

__device__ __forceinline__ void mma16816(float* c, const uint4& a, const uint2& b) {
    asm volatile("mma.sync.aligned.m16n8k16.row.col.f32.f16.f16.f32 "
                 "{%0,%1,%2,%3}, {%4,%5,%6,%7}, {%8,%9}, {%0,%1,%2,%3};"
                 : "+f"(c[0]), "+f"(c[1]), "+f"(c[2]), "+f"(c[3])
                 : "r"(a.x), "r"(a.y), "r"(a.z), "r"(a.w), "r"(b.x), "r"(b.y));
}
// 2-term: (W_hi + W_lo) x h_hi. This warp's 2 k-slices of one chunk.
__device__ __forceinline__ void compute_chunk(float acc[4][4], const char* stg,
                                              int w8, int t, int sbase) {
    const char* Bb = stg + CHW;
    #pragma unroll
    for (int ss = 0; ss < 2; ss++) {
        int s = sbase + ss;
        uint4 ahi = *(const uint4*)(stg + ((((s * 2 + 0) * 8 + w8) * 32 + t) << 4));
        uint4 alo = *(const uint4*)(stg + ((((s * 2 + 1) * 8 + w8) * 32 + t) << 4));
        #pragma unroll
        for (int nt = 0; nt < 4; nt++) {
            uint2 bhi = *(const uint2*)(Bb + (((s * 4 + nt) * 32 + t) << 3));
            mma16816(acc[nt], ahi, bhi);
            mma16816(acc[nt], alo, bhi);
        }
    }
}
__device__ __forceinline__ void c_chunk(float acc[4][4], char* sm, u32 smb, int g,
                                        int w8, int t, int sbase, int lane) {
    int slot = g & 3;
    wait_par(smb + MB_OFF + slot * 8, (u32)((g >> 2) & 1));
    compute_chunk(acc, sm + slot * STGB, w8, t, sbase);
    __syncwarp();
    if (lane == 0) mbar_arrive(smb + MB_OFF + 32 + slot * 8);
}
__device__ __forceinline__ void store_gbuf(float* g, float acc[4][4], int w8, int t, int kg) {
    float* gk = g + kg * 4224;
    int q = w8 * 16 + (t >> 2), c0 = (t & 3) * 2;
    #pragma unroll
    for (int nt = 0; nt < 4; nt++) {
        int c = nt * 8 + c0;
        gk[q * 33 + c] = acc[nt][0];       gk[q * 33 + c + 1] = acc[nt][1];
        gk[(q + 8) * 33 + c] = acc[nt][2]; gk[(q + 8) * 33 + c + 1] = acc[nt][3];
    }
}
// write 2 units of h (batch bl) as fp16-hi into B-fragment slab
__device__ __forceinline__ void write_h2(unsigned char* cb, int u0, int bl, const float* hv) {
    int s = (u0 & 63) >> 4, kk0 = u0 & 15, r = kk0 >> 3;
    int tf = (bl & 7) * 4 + ((kk0 & 7) >> 1), nt = bl >> 3;
    u32 hiw = (u32)__half_as_ushort(__float2half_rn(hv[0]))
            | ((u32)__half_as_ushort(__float2half_rn(hv[1])) << 16);
    *(u32*)(cb + (((s * 4 + nt) * 32 + tf) * 8 + r * 4)) = hiw;
}
#define CBAR() asm volatile("bar.sync 1, 512;" ::: "memory")

__global__ void __launch_bounds__(544, 1) lstm_mma(
    const float* __restrict__ blin,
    const int* __restrict__ z, const int* __restrict__ nframes,
    float* __restrict__ out)
{
    extern __shared__ __align__(16) char sm[];
    u32 smb = (u32)__cvta_generic_to_shared(sm);
    float* gbuf = (float*)(sm + GB_OFF);
    const int tid = threadIdx.x, lane = tid & 31, wid = tid >> 5;
    const int w8 = wid & 7, kg = wid >> 3, sbase = kg * 2;
    const int blk = blockIdx.x;

    if (tid == 0) {
        #pragma unroll
        for (int s = 0; s < NS; s++) {
            mbar_init(smb + MB_OFF + s * 8, 1);        // full
            mbar_init(smb + MB_OFF + 32 + s * 8, 16);  // empty: 16 consumer warps
        }
    }
    __syncthreads();

    if (blk < 128) {
        const int st = blk >> 3, bt = blk & 7;
        if (wid == 16) {  // producer
            if (lane == 0) {
                int g = 0;
                for (int t = 0; t < NT; t++) {
                    const int rd = t & 1, wr = rd ^ 1;
                    poll_epoch(2 * t - 2);
                    for (int ch = 0; ch < 8; ch++, g++)
                        p_issue(smb, g, g_w0f[st][ch], g_h0f[rd][bt][ch]);
                    poll_epoch(2 * t - 1);
                    for (int ch = 0; ch < 8; ch++, g++)
                        p_issue(smb, g, g_w1f[st][8 + ch], g_h1f[rd][bt][ch]);
                    poll_epoch(2 * t);
                    for (int ch = 0; ch < 8; ch++, g++)
                        p_issue(smb, g, g_w1f[st][ch], g_h0f[wr][bt][ch]);
                }
            }
        } else {          // 16 consumer warps
            const int bl = tid & 31, uu2 = (tid >> 5) * 2;
            const int gb = bt * 32 + bl, hch = st >> 1;
            int g = 0;
            for (int t = 0; t < NT; t++) {
                const int rd = t & 1, wr = rd ^ 1;
                float acc[4][4] = {};
                for (int ch = 0; ch < 8; ch++, g++)
                    c_chunk(acc, sm, smb, g, w8, lane, sbase, lane);
                store_gbuf(gbuf, acc, w8, lane, kg);
                CBAR();
                const float* lut = (t > 0) ? g_lut + (size_t)z[gb * NT + t - 1] * 2048 : nullptr;
                float hv[2];
                #pragma unroll
                for (int q = 0; q < 2; q++) {
                    int uu = uu2 + q, ug = st * 32 + uu;
                    float gi = gbuf[uu * 33 + bl]        + gbuf[4224 + uu * 33 + bl]        + g_bs0[ug];
                    float gf = gbuf[(32 + uu) * 33 + bl] + gbuf[4224 + (32 + uu) * 33 + bl] + g_bs0[512 + ug];
                    float gg = gbuf[(64 + uu) * 33 + bl] + gbuf[4224 + (64 + uu) * 33 + bl] + g_bs0[1024 + ug];
                    float go = gbuf[(96 + uu) * 33 + bl] + gbuf[4224 + (96 + uu) * 33 + bl] + g_bs0[1536 + ug];
                    if (lut) { gi += lut[ug]; gf += lut[512 + ug]; gg += lut[1024 + ug]; go += lut[1536 + ug]; }
                    int ci = ug * NB + gb;
                    float c = g_c0[ci];
                    float cn = sigf(gf) * c + sigf(gi) * tanhf_fast(gg);
                    g_c0[ci] = cn;
                    hv[q] = sigf(go) * tanhf_fast(cn);
                }
                write_h2(g_h0f[wr][bt][hch], st * 32 + uu2, bl, hv);
                __threadfence();
                CBAR();
                if (tid == 0) atomicAdd(&g_cnt[(2 * t) & 3], 1u);

                #pragma unroll
                for (int nt = 0; nt < 4; nt++)
                    #pragma unroll
                    for (int q = 0; q < 4; q++) acc[nt][q] = 0.f;
                for (int ch = 0; ch < 16; ch++, g++)
                    c_chunk(acc, sm, smb, g, w8, lane, sbase, lane);
                store_gbuf(gbuf, acc, w8, lane, kg);
                CBAR();
                #pragma unroll
                for (int q = 0; q < 2; q++) {
                    int uu = uu2 + q, ug = st * 32 + uu;
                    float gi = gbuf[uu * 33 + bl]        + gbuf[4224 + uu * 33 + bl]        + g_bs1[ug];
                    float gf = gbuf[(32 + uu) * 33 + bl] + gbuf[4224 + (32 + uu) * 33 + bl] + g_bs1[512 + ug];
                    float gg = gbuf[(64 + uu) * 33 + bl] + gbuf[4224 + (64 + uu) * 33 + bl] + g_bs1[1024 + ug];
                    float go = gbuf[(96 + uu) * 33 + bl] + gbuf[4224 + (96 + uu) * 33 + bl] + g_bs1[1536 + ug];
                    int ci = ug * NB + gb;
                    float c = g_c1[ci];
                    float cn = sigf(gf) * c + sigf(gi) * tanhf_fast(gg);
                    g_c1[ci] = cn;
                    hv[q] = sigf(go) * tanhf_fast(cn);
                }
                write_h2(g_h1f[wr][bt][hch], st * 32 + uu2, bl, hv);
                __threadfence();
                CBAR();
                if (tid == 0) atomicAdd(&g_cnt[(2 * t + 1) & 3], 1u);
            }
        }
    } else {
        // ---------- logits CTA ----------
        const int bt = blk - 128, b0 = bt * 32;
        if (wid == 16) {
            if (lane == 0) {
                int g = 0;
                for (int t = 1; t <= NT; t++) {
                    const int rd = t & 1;
                    poll_epoch(2 * t - 1);
                    for (int ch = 0; ch < 8; ch++, g++)
                        p_issue(smb, g, g_wlf[ch], g_h1f[rd][bt][ch]);
                }
            }
        } else {
            float nll[2];
            int nf2[2];
            #pragma unroll
            for (int j = 0; j < 2; j++) { nll[j] = 0.f; nf2[j] = nframes[b0 + wid * 2 + j]; }
            int g = 0;
            for (int t = 0; t <= NT; t++) {
                if (t >= 1) {
                    const int s = t - 1;
                    float acc[4][4] = {};
                    for (int ch = 0; ch < 8; ch++, g++)
                        c_chunk(acc, sm, smb, g, w8, lane, sbase, lane);
                    store_gbuf(gbuf, acc, w8, lane, kg);
                    CBAR();
                    float bl4[4];
                    #pragma unroll
                    for (int q = 0; q < 4; q++) bl4[q] = blin[lane + 32 * q];
                    #pragma unroll
                    for (int j = 0; j < 2; j++) {
                        int blr = wid * 2 + j;
                        float lg[4];
                        #pragma unroll
                        for (int q = 0; q < 4; q++)
                            lg[q] = gbuf[(lane + 32 * q) * 33 + blr]
                                  + gbuf[4224 + (lane + 32 * q) * 33 + blr] + bl4[q];
                        float m = fmaxf(fmaxf(lg[0], lg[1]), fmaxf(lg[2], lg[3]));
                        m = warp_max(m);
                        float se = 0.f;
                        #pragma unroll
                        for (int q = 0; q < 4; q++) se += __expf(lg[q] - m);
                        se = warp_sum(se);
                        float lse = m + logf(se);
                        int tgt = z[(b0 + blr) * NT + s];
                        float tl = 0.f;
                        #pragma unroll
                        for (int q = 0; q < 4; q++)
                            if (lane + 32 * q == tgt) tl = lg[q];
                        tl = warp_sum(tl);
                        if (s < nf2[j]) nll[j] += (lse - tl);
                    }
                    CBAR();
                }
                if (t < NT) {
                    CBAR();
                    if (tid == 0) {
                        atomicAdd(&g_cnt[(2 * t) & 3], 1u);
                        atomicAdd(&g_cnt[(2 * t + 1) & 3], 1u);
                    }
                }
            }
            if (lane == 0) {
                #pragma unroll
                for (int j = 0; j < 2; j++)
                    out[b0 + wid * 2 + j] = nll[j] * (1.0f / (float)NT);
            }
        }
    }
}

extern "C" void kernel_launch(void* const* d_in, const int* in_sizes, int n_in,
                              void* d_out, int out_size) {
    const float* Wih0 = (const float*)d_in[0];
    const float* Whh0 = (const float*)d_in[1];
    const float* bih0 = (const float*)d_in[2];
    const float* bhh0 = (const float*)d_in[3];
    const float* Wih1 = (const float*)d_in[4];
    const float* Whh1 = (const float*)d_in[5];
    const float* bih1 = (const float*)d_in[6];
    const float* bhh1 = (const float*)d_in[7];
    const float* Wlin = (const float*)d_in[8];
    const float* blin = (const float*)d_in[9];
    const int*   z    = (const int*)d_in[10];
    const int*   nf   = (const int*)d_in[11];
    float* out = (float*)d_out;

    cudaFuncSetAttribute(lstm_mma, cudaFuncAttributeMaxDynamicSharedMemorySize, SMEM_DYN);
    kinit<<<256, 256>>>(Wih0, Whh0, bih0, bhh0, Wih1, Whh1, bih1, bhh1, Wlin);
    lstm_mma<<<GRID, 544, SMEM_DYN>>>(blin, z, nf, out);
}